// round 4
// baseline (speedup 1.0000x reference)
#include <cuda_runtime.h>

// ---------------------------------------------------------------------------
// SMPNLayer: edge-message MLP + segment-sum + node-update MLP (all fp32).
//
// Decomposition: msg_in @ W1 = nf[src]@W1a + nf[dst]@W1b + ef@W1c + st[src]@W1d
//   PR[n] = nf[n]@W1a + st[n]@W1d   (precomputed per node)
//   Q [n] = nf[n]@W1b               (precomputed per node)
//   h1(e) = relu(PR[src] + Q[dst] + ef[e]@W1c + b1)
//
// All GEMM loops use packed fp32x2 FMA (fma.rn.f32x2) with edge-pair-packed
// transposed activations in shared memory.
// ---------------------------------------------------------------------------

typedef unsigned long long u64;

__device__ __forceinline__ u64 pack2(float lo, float hi) {
    u64 r;
    asm("mov.b64 %0, {%1, %2};" : "=l"(r) : "f"(lo), "f"(hi));
    return r;
}
__device__ __forceinline__ void unpack2(u64 v, float& lo, float& hi) {
    asm("mov.b64 {%0, %1}, %2;" : "=f"(lo), "=f"(hi) : "l"(v));
}
__device__ __forceinline__ u64 fma2(u64 a, u64 b, u64 c) {
    u64 d;
    asm("fma.rn.f32x2 %0, %1, %2, %3;" : "=l"(d) : "l"(a), "l"(b), "l"(c));
    return d;
}

// One k-step: acc[4 edge-pairs][4 cols] += A_pairs[k] * Wrow[cg*4 .. cg*4+3]
__device__ __forceinline__ void step128(u64 acc[4][4], const float* __restrict__ wrow,
                                        const float* sA, int cg) {
    float4 w = __ldg(reinterpret_cast<const float4*>(wrow + cg * 4));
    u64 w0 = pack2(w.x, w.x), w1 = pack2(w.y, w.y);
    u64 w2 = pack2(w.z, w.z), w3 = pack2(w.w, w.w);
    const u64* ap = reinterpret_cast<const u64*>(sA);
#pragma unroll
    for (int p = 0; p < 4; p++) {
        u64 a = ap[p];
        acc[p][0] = fma2(a, w0, acc[p][0]);
        acc[p][1] = fma2(a, w1, acc[p][1]);
        acc[p][2] = fma2(a, w2, acc[p][2]);
        acc[p][3] = fma2(a, w3, acc[p][3]);
    }
}

// One k-step for 64-wide output: acc[4 pairs][2 cols]
__device__ __forceinline__ void step64(u64 acc[4][2], const float* __restrict__ wrow,
                                       const float* sA, int cg) {
    float2 w = __ldg(reinterpret_cast<const float2*>(wrow + cg * 2));
    u64 w0 = pack2(w.x, w.x), w1 = pack2(w.y, w.y);
    const u64* ap = reinterpret_cast<const u64*>(sA);
#pragma unroll
    for (int p = 0; p < 4; p++) {
        u64 a = ap[p];
        acc[p][0] = fma2(a, w0, acc[p][0]);
        acc[p][1] = fma2(a, w1, acc[p][1]);
    }
}

// Scratch for per-node precomputed layer-1 partials (50000 x 128 each)
__device__ float g_PR[50000 * 128];
__device__ float g_Q [50000 * 128];

// ---------------------------------------------------------------------------
// K1: PR[n] = nf[n] @ W1[0:64]   + st[n] @ W1[160:192]
//     Q [n] = nf[n] @ W1[64:128]
// Tile: 64 nodes / block, 256 threads.
// ---------------------------------------------------------------------------
__global__ __launch_bounds__(256) void node_pre_kernel(
    const float* __restrict__ nf, const float* __restrict__ st,
    const float* __restrict__ mW1,
    float* __restrict__ PR, float* __restrict__ Qv, int n_nodes)
{
    __shared__ __align__(16) float s_nfT[64 * 64];  // [k][node]
    __shared__ __align__(16) float s_stT[32 * 64];
    const int tid = threadIdx.x;
    const int n0 = blockIdx.x * 64;

    for (int s = tid; s < 64 * 16; s += 256) {
        int n = s >> 4, k4 = s & 15;
        int ng = min(n0 + n, n_nodes - 1);
        float4 v = __ldg(reinterpret_cast<const float4*>(nf) + (size_t)ng * 16 + k4);
        s_nfT[(k4 * 4 + 0) * 64 + n] = v.x;
        s_nfT[(k4 * 4 + 1) * 64 + n] = v.y;
        s_nfT[(k4 * 4 + 2) * 64 + n] = v.z;
        s_nfT[(k4 * 4 + 3) * 64 + n] = v.w;
    }
    for (int s = tid; s < 64 * 8; s += 256) {
        int n = s >> 3, k4 = s & 7;
        int ng = min(n0 + n, n_nodes - 1);
        float4 v = __ldg(reinterpret_cast<const float4*>(st) + (size_t)ng * 8 + k4);
        s_stT[(k4 * 4 + 0) * 64 + n] = v.x;
        s_stT[(k4 * 4 + 1) * 64 + n] = v.y;
        s_stT[(k4 * 4 + 2) * 64 + n] = v.z;
        s_stT[(k4 * 4 + 3) * 64 + n] = v.w;
    }
    __syncthreads();

    const int cg = tid & 31;
    const int nb = (tid >> 5) * 8;

    u64 acc[4][4];
#pragma unroll
    for (int p = 0; p < 4; p++)
#pragma unroll
        for (int j = 0; j < 4; j++) acc[p][j] = 0ull;

#pragma unroll 8
    for (int k = 0; k < 64; k++)
        step128(acc, mW1 + (size_t)k * 128, s_nfT + k * 64 + nb, cg);
#pragma unroll 8
    for (int k = 0; k < 32; k++)
        step128(acc, mW1 + (size_t)(160 + k) * 128, s_stT + k * 64 + nb, cg);

#pragma unroll
    for (int p = 0; p < 4; p++) {
        int nA = n0 + nb + 2 * p, nB = nA + 1;
#pragma unroll
        for (int j = 0; j < 4; j++) {
            float xA, xB; unpack2(acc[p][j], xA, xB);
            if (nA < n_nodes) PR[(size_t)nA * 128 + cg * 4 + j] = xA;
            if (nB < n_nodes) PR[(size_t)nB * 128 + cg * 4 + j] = xB;
        }
    }

    // Q = nf @ W1b
#pragma unroll
    for (int p = 0; p < 4; p++)
#pragma unroll
        for (int j = 0; j < 4; j++) acc[p][j] = 0ull;
#pragma unroll 8
    for (int k = 0; k < 64; k++)
        step128(acc, mW1 + (size_t)(64 + k) * 128, s_nfT + k * 64 + nb, cg);

#pragma unroll
    for (int p = 0; p < 4; p++) {
        int nA = n0 + nb + 2 * p, nB = nA + 1;
#pragma unroll
        for (int j = 0; j < 4; j++) {
            float xA, xB; unpack2(acc[p][j], xA, xB);
            if (nA < n_nodes) Qv[(size_t)nA * 128 + cg * 4 + j] = xA;
            if (nB < n_nodes) Qv[(size_t)nB * 128 + cg * 4 + j] = xB;
        }
    }
}

// ---------------------------------------------------------------------------
// K2: node update MLP: out = nf + relu(cat(nf,st)@uW1 + ub1)@uW2 + ub2
//     Also zeros the aggregation half of the output.
// Tile: 64 nodes / block, 256 threads.
// ---------------------------------------------------------------------------
__global__ __launch_bounds__(256) void update_kernel(
    const float* __restrict__ nf, const float* __restrict__ st,
    const float* __restrict__ uW1, const float* __restrict__ ub1,
    const float* __restrict__ uW2, const float* __restrict__ ub2,
    float* __restrict__ out_nodes, float* __restrict__ agg, int n_nodes)
{
    __shared__ __align__(16) float s_buf[128 * 64];  // uT[96][64] then hT[128][64]
    __shared__ float s_ub1[128];
    __shared__ float s_ub2[64];
    const int tid = threadIdx.x;
    const int n0 = blockIdx.x * 64;

    // zero the aggregation rows for this tile (must happen before edge kernel)
    for (int i = tid; i < 64 * 64; i += 256) {
        int n = n0 + (i >> 6);
        if (n < n_nodes) agg[(size_t)n * 64 + (i & 63)] = 0.f;
    }
    for (int i = tid; i < 192; i += 256) {
        if (i < 128) s_ub1[i] = ub1[i];
        else         s_ub2[i - 128] = ub2[i - 128];
    }
    // load transposed input: rows 0..63 = nf, rows 64..95 = st
    for (int s = tid; s < 64 * 16; s += 256) {
        int n = s >> 4, k4 = s & 15;
        int ng = min(n0 + n, n_nodes - 1);
        float4 v = __ldg(reinterpret_cast<const float4*>(nf) + (size_t)ng * 16 + k4);
        s_buf[(k4 * 4 + 0) * 64 + n] = v.x;
        s_buf[(k4 * 4 + 1) * 64 + n] = v.y;
        s_buf[(k4 * 4 + 2) * 64 + n] = v.z;
        s_buf[(k4 * 4 + 3) * 64 + n] = v.w;
    }
    for (int s = tid; s < 64 * 8; s += 256) {
        int n = s >> 3, k4 = s & 7;
        int ng = min(n0 + n, n_nodes - 1);
        float4 v = __ldg(reinterpret_cast<const float4*>(st) + (size_t)ng * 8 + k4);
        s_buf[(64 + k4 * 4 + 0) * 64 + n] = v.x;
        s_buf[(64 + k4 * 4 + 1) * 64 + n] = v.y;
        s_buf[(64 + k4 * 4 + 2) * 64 + n] = v.z;
        s_buf[(64 + k4 * 4 + 3) * 64 + n] = v.w;
    }
    __syncthreads();

    const int cg = tid & 31;
    const int nb = (tid >> 5) * 8;

    u64 acc[4][4];
#pragma unroll
    for (int p = 0; p < 4; p++)
#pragma unroll
        for (int j = 0; j < 4; j++) acc[p][j] = 0ull;
#pragma unroll 8
    for (int k = 0; k < 96; k++)
        step128(acc, uW1 + (size_t)k * 128, s_buf + k * 64 + nb, cg);

    __syncthreads();  // all reads of uT done before overwrite with hT
#pragma unroll
    for (int p = 0; p < 4; p++) {
        int eA = nb + 2 * p;
#pragma unroll
        for (int j = 0; j < 4; j++) {
            float xA, xB; unpack2(acc[p][j], xA, xB);
            float bb = s_ub1[cg * 4 + j];
            xA = fmaxf(xA + bb, 0.f);
            xB = fmaxf(xB + bb, 0.f);
            *reinterpret_cast<u64*>(s_buf + (cg * 4 + j) * 64 + eA) = pack2(xA, xB);
        }
    }
    __syncthreads();

    u64 acc2[4][2];
#pragma unroll
    for (int p = 0; p < 4; p++) { acc2[p][0] = 0ull; acc2[p][1] = 0ull; }
#pragma unroll 8
    for (int k = 0; k < 128; k++)
        step64(acc2, uW2 + (size_t)k * 64, s_buf + k * 64 + nb, cg);

    const int c2 = cg * 2;
    float b0 = s_ub2[c2], b1v = s_ub2[c2 + 1];
#pragma unroll
    for (int p = 0; p < 4; p++) {
        int nA = n0 + nb + 2 * p, nB = nA + 1;
        float xA, xB, yA, yB;
        unpack2(acc2[p][0], xA, xB);
        unpack2(acc2[p][1], yA, yB);
        if (nA < n_nodes) {
            float2 r = __ldg(reinterpret_cast<const float2*>(nf + (size_t)nA * 64 + c2));
            float2 o; o.x = xA + b0 + r.x; o.y = yA + b1v + r.y;
            *reinterpret_cast<float2*>(out_nodes + (size_t)nA * 64 + c2) = o;
        }
        if (nB < n_nodes) {
            float2 r = __ldg(reinterpret_cast<const float2*>(nf + (size_t)nB * 64 + c2));
            float2 o; o.x = xB + b0 + r.x; o.y = yB + b1v + r.y;
            *reinterpret_cast<float2*>(out_nodes + (size_t)nB * 64 + c2) = o;
        }
    }
}

// ---------------------------------------------------------------------------
// K3: per-edge message MLP + atomic aggregation.
//   h1 = relu(ef@W1c + PR[src] + Q[dst] + b1)
//   h2 = relu(h1@W2 + b2)
//   msg = h2@W3 + b3  -> atomicAdd into agg[dst]
// Tile: 64 edges / block, 256 threads. Activations live transposed in smem,
// h1 and h2 share one buffer (sync-guarded overwrite).
// ---------------------------------------------------------------------------
__global__ __launch_bounds__(256) void edge_kernel(
    const float* __restrict__ ef, const int* __restrict__ eidx,
    const float* __restrict__ mW1, const float* __restrict__ mb1,
    const float* __restrict__ mW2, const float* __restrict__ mb2,
    const float* __restrict__ mW3, const float* __restrict__ mb3,
    const float* __restrict__ PR, const float* __restrict__ Qv,
    float* __restrict__ agg, int n_edges)
{
    __shared__ __align__(16) float s_efT[32 * 64];   // [k][edge]
    __shared__ __align__(16) float s_hT[128 * 64];   // h1 then h2, [c][edge]
    __shared__ int s_src[64], s_dst[64];
    __shared__ float s_b1[128], s_b2[128], s_b3[64];

    const int tid = threadIdx.x;
    const int e0 = blockIdx.x * 64;

    if (tid < 64) {
        int ee = min(e0 + tid, n_edges - 1);
        int2 pr_ = __ldg(reinterpret_cast<const int2*>(eidx) + ee);
        s_src[tid] = pr_.x;
        s_dst[tid] = pr_.y;
    }
    for (int i = tid; i < 320; i += 256) {
        if (i < 128)      s_b1[i] = mb1[i];
        else if (i < 256) s_b2[i - 128] = mb2[i - 128];
        else              s_b3[i - 256] = mb3[i - 256];
    }
    for (int s = tid; s < 64 * 8; s += 256) {
        int e = s >> 3, k4 = s & 7;
        int ee = min(e0 + e, n_edges - 1);
        float4 v = __ldg(reinterpret_cast<const float4*>(ef) + (size_t)ee * 8 + k4);
        s_efT[(k4 * 4 + 0) * 64 + e] = v.x;
        s_efT[(k4 * 4 + 1) * 64 + e] = v.y;
        s_efT[(k4 * 4 + 2) * 64 + e] = v.z;
        s_efT[(k4 * 4 + 3) * 64 + e] = v.w;
    }
    __syncthreads();

    const int cg = tid & 31;
    const int nb = (tid >> 5) * 8;

    // ---- layer 1 (K=32, W1c = mW1 rows 128..159) ----
    u64 acc[4][4];
#pragma unroll
    for (int p = 0; p < 4; p++)
#pragma unroll
        for (int j = 0; j < 4; j++) acc[p][j] = 0ull;
#pragma unroll 8
    for (int k = 0; k < 32; k++)
        step128(acc, mW1 + (size_t)(128 + k) * 128, s_efT + k * 64 + nb, cg);

    // epilogue: + PR[src] + Q[dst] + b1, relu, write transposed h1
#pragma unroll
    for (int p = 0; p < 4; p++) {
        int eA = nb + 2 * p, eB = eA + 1;
        int sA = s_src[eA], sB = s_src[eB];
        int dA = s_dst[eA], dB = s_dst[eB];
        float4 prA = __ldg(reinterpret_cast<const float4*>(PR + (size_t)sA * 128 + cg * 4));
        float4 prB = __ldg(reinterpret_cast<const float4*>(PR + (size_t)sB * 128 + cg * 4));
        float4 qA  = __ldg(reinterpret_cast<const float4*>(Qv + (size_t)dA * 128 + cg * 4));
        float4 qB  = __ldg(reinterpret_cast<const float4*>(Qv + (size_t)dB * 128 + cg * 4));
        float pa[4] = {prA.x, prA.y, prA.z, prA.w};
        float pb[4] = {prB.x, prB.y, prB.z, prB.w};
        float qa[4] = {qA.x, qA.y, qA.z, qA.w};
        float qb[4] = {qB.x, qB.y, qB.z, qB.w};
#pragma unroll
        for (int j = 0; j < 4; j++) {
            float xA, xB; unpack2(acc[p][j], xA, xB);
            float bb = s_b1[cg * 4 + j];
            xA = fmaxf(xA + pa[j] + qa[j] + bb, 0.f);
            xB = fmaxf(xB + pb[j] + qb[j] + bb, 0.f);
            *reinterpret_cast<u64*>(s_hT + (cg * 4 + j) * 64 + eA) = pack2(xA, xB);
        }
    }
    __syncthreads();

    // ---- layer 2 (K=128) ----
    u64 acc2[4][4];
#pragma unroll
    for (int p = 0; p < 4; p++)
#pragma unroll
        for (int j = 0; j < 4; j++) acc2[p][j] = 0ull;
#pragma unroll 8
    for (int k = 0; k < 128; k++)
        step128(acc2, mW2 + (size_t)k * 128, s_hT + k * 64 + nb, cg);

    __syncthreads();  // all h1 reads done before overwriting with h2
#pragma unroll
    for (int p = 0; p < 4; p++) {
        int eA = nb + 2 * p;
#pragma unroll
        for (int j = 0; j < 4; j++) {
            float xA, xB; unpack2(acc2[p][j], xA, xB);
            float bb = s_b2[cg * 4 + j];
            xA = fmaxf(xA + bb, 0.f);
            xB = fmaxf(xB + bb, 0.f);
            *reinterpret_cast<u64*>(s_hT + (cg * 4 + j) * 64 + eA) = pack2(xA, xB);
        }
    }
    __syncthreads();

    // ---- layer 3 (K=128, 64 out cols) ----
    u64 acc3[4][2];
#pragma unroll
    for (int p = 0; p < 4; p++) { acc3[p][0] = 0ull; acc3[p][1] = 0ull; }
#pragma unroll 8
    for (int k = 0; k < 128; k++)
        step64(acc3, mW3 + (size_t)k * 64, s_hT + k * 64 + nb, cg);

    const int c2 = cg * 2;
    float bb0 = s_b3[c2], bb1 = s_b3[c2 + 1];
#pragma unroll
    for (int p = 0; p < 4; p++) {
        int eA = nb + 2 * p, eB = eA + 1;
        float xA, xB, yA, yB;
        unpack2(acc3[p][0], xA, xB);
        unpack2(acc3[p][1], yA, yB);
        if (e0 + eA < n_edges) {
            int dA = s_dst[eA];
            atomicAdd(agg + (size_t)dA * 64 + c2,     xA + bb0);
            atomicAdd(agg + (size_t)dA * 64 + c2 + 1, yA + bb1);
        }
        if (e0 + eB < n_edges) {
            int dB = s_dst[eB];
            atomicAdd(agg + (size_t)dB * 64 + c2,     xB + bb0);
            atomicAdd(agg + (size_t)dB * 64 + c2 + 1, yB + bb1);
        }
    }
}

// ---------------------------------------------------------------------------
extern "C" void kernel_launch(void* const* d_in, const int* in_sizes, int n_in,
                              void* d_out, int out_size)
{
    const float* nf  = (const float*)d_in[0];
    const float* ef  = (const float*)d_in[1];
    const float* st  = (const float*)d_in[2];
    const float* mW1 = (const float*)d_in[3];
    const float* mb1 = (const float*)d_in[4];
    const float* mW2 = (const float*)d_in[5];
    const float* mb2 = (const float*)d_in[6];
    const float* mW3 = (const float*)d_in[7];
    const float* mb3 = (const float*)d_in[8];
    const float* uW1 = (const float*)d_in[9];
    const float* ub1 = (const float*)d_in[10];
    const float* uW2 = (const float*)d_in[11];
    const float* ub2 = (const float*)d_in[12];
    const int*   eidx = (const int*)d_in[13];

    const int n_nodes = in_sizes[0] / 64;
    const int n_edges = in_sizes[1] / 32;

    float* out_nodes = (float*)d_out;
    float* agg = out_nodes + (size_t)n_nodes * 64;

    float *PR = nullptr, *Qv = nullptr;
    cudaGetSymbolAddress((void**)&PR, g_PR);
    cudaGetSymbolAddress((void**)&Qv, g_Q);

    const int nblocks = (n_nodes + 63) / 64;
    const int eblocks = (n_edges + 63) / 64;

    node_pre_kernel<<<nblocks, 256>>>(nf, st, mW1, PR, Qv, n_nodes);
    update_kernel<<<nblocks, 256>>>(nf, st, uW1, ub1, uW2, ub2, out_nodes, agg, n_nodes);
    edge_kernel<<<eblocks, 256>>>(ef, eidx, mW1, mb1, mW2, mb2, mW3, mb3, PR, Qv, agg, n_edges);
}

// round 5
// speedup vs baseline: 1.0011x; 1.0011x over previous
#include <cuda_runtime.h>

// ---------------------------------------------------------------------------
// SMPNLayer: edge-message MLP + segment-sum + node-update MLP (all fp32).
//
// Decomposition: msg_in @ W1 = nf[src]@W1a + nf[dst]@W1b + ef@W1c + st[src]@W1d
//   PR[n] = nf[n]@W1a + st[n]@W1d   (precomputed per node)
//   Q [n] = nf[n]@W1b               (precomputed per node)
//   h1(e) = relu(PR[src] + Q[dst] + ef[e]@W1c + b1)
//
// All GEMM loops use packed fp32x2 FMA (fma.rn.f32x2) with edge-pair-packed
// transposed activations in shared memory.
// ---------------------------------------------------------------------------

typedef unsigned long long u64;

__device__ __forceinline__ u64 pack2(float lo, float hi) {
    u64 r;
    asm("mov.b64 %0, {%1, %2};" : "=l"(r) : "f"(lo), "f"(hi));
    return r;
}
__device__ __forceinline__ void unpack2(u64 v, float& lo, float& hi) {
    asm("mov.b64 {%0, %1}, %2;" : "=f"(lo), "=f"(hi) : "l"(v));
}
__device__ __forceinline__ u64 fma2(u64 a, u64 b, u64 c) {
    u64 d;
    asm("fma.rn.f32x2 %0, %1, %2, %3;" : "=l"(d) : "l"(a), "l"(b), "l"(c));
    return d;
}

// One k-step: acc[4 edge-pairs][4 cols] += A_pairs[k] * Wrow[cg*4 .. cg*4+3]
__device__ __forceinline__ void step128(u64 acc[4][4], const float* __restrict__ wrow,
                                        const float* sA, int cg) {
    float4 w = __ldg(reinterpret_cast<const float4*>(wrow + cg * 4));
    u64 w0 = pack2(w.x, w.x), w1 = pack2(w.y, w.y);
    u64 w2 = pack2(w.z, w.z), w3 = pack2(w.w, w.w);
    const u64* ap = reinterpret_cast<const u64*>(sA);
#pragma unroll
    for (int p = 0; p < 4; p++) {
        u64 a = ap[p];
        acc[p][0] = fma2(a, w0, acc[p][0]);
        acc[p][1] = fma2(a, w1, acc[p][1]);
        acc[p][2] = fma2(a, w2, acc[p][2]);
        acc[p][3] = fma2(a, w3, acc[p][3]);
    }
}

// One k-step for 64-wide output: acc[4 pairs][2 cols]
__device__ __forceinline__ void step64(u64 acc[4][2], const float* __restrict__ wrow,
                                       const float* sA, int cg) {
    float2 w = __ldg(reinterpret_cast<const float2*>(wrow + cg * 2));
    u64 w0 = pack2(w.x, w.x), w1 = pack2(w.y, w.y);
    const u64* ap = reinterpret_cast<const u64*>(sA);
#pragma unroll
    for (int p = 0; p < 4; p++) {
        u64 a = ap[p];
        acc[p][0] = fma2(a, w0, acc[p][0]);
        acc[p][1] = fma2(a, w1, acc[p][1]);
    }
}

// Scratch for per-node precomputed layer-1 partials (50000 x 128 each)
__device__ float g_PR[50000 * 128];
__device__ float g_Q [50000 * 128];

// ---------------------------------------------------------------------------
// K1: PR[n] = nf[n] @ W1[0:64]   + st[n] @ W1[160:192]
//     Q [n] = nf[n] @ W1[64:128]
// Tile: 64 nodes / block, 256 threads.
// ---------------------------------------------------------------------------
__global__ __launch_bounds__(256) void node_pre_kernel(
    const float* __restrict__ nf, const float* __restrict__ st,
    const float* __restrict__ mW1,
    float* __restrict__ PR, float* __restrict__ Qv, int n_nodes)
{
    __shared__ __align__(16) float s_nfT[64 * 64];  // [k][node]
    __shared__ __align__(16) float s_stT[32 * 64];
    const int tid = threadIdx.x;
    const int n0 = blockIdx.x * 64;

    for (int s = tid; s < 64 * 16; s += 256) {
        int n = s >> 4, k4 = s & 15;
        int ng = min(n0 + n, n_nodes - 1);
        float4 v = __ldg(reinterpret_cast<const float4*>(nf) + (size_t)ng * 16 + k4);
        s_nfT[(k4 * 4 + 0) * 64 + n] = v.x;
        s_nfT[(k4 * 4 + 1) * 64 + n] = v.y;
        s_nfT[(k4 * 4 + 2) * 64 + n] = v.z;
        s_nfT[(k4 * 4 + 3) * 64 + n] = v.w;
    }
    for (int s = tid; s < 64 * 8; s += 256) {
        int n = s >> 3, k4 = s & 7;
        int ng = min(n0 + n, n_nodes - 1);
        float4 v = __ldg(reinterpret_cast<const float4*>(st) + (size_t)ng * 8 + k4);
        s_stT[(k4 * 4 + 0) * 64 + n] = v.x;
        s_stT[(k4 * 4 + 1) * 64 + n] = v.y;
        s_stT[(k4 * 4 + 2) * 64 + n] = v.z;
        s_stT[(k4 * 4 + 3) * 64 + n] = v.w;
    }
    __syncthreads();

    const int cg = tid & 31;
    const int nb = (tid >> 5) * 8;

    u64 acc[4][4];
#pragma unroll
    for (int p = 0; p < 4; p++)
#pragma unroll
        for (int j = 0; j < 4; j++) acc[p][j] = 0ull;

#pragma unroll 8
    for (int k = 0; k < 64; k++)
        step128(acc, mW1 + (size_t)k * 128, s_nfT + k * 64 + nb, cg);
#pragma unroll 8
    for (int k = 0; k < 32; k++)
        step128(acc, mW1 + (size_t)(160 + k) * 128, s_stT + k * 64 + nb, cg);

#pragma unroll
    for (int p = 0; p < 4; p++) {
        int nA = n0 + nb + 2 * p, nB = nA + 1;
#pragma unroll
        for (int j = 0; j < 4; j++) {
            float xA, xB; unpack2(acc[p][j], xA, xB);
            if (nA < n_nodes) PR[(size_t)nA * 128 + cg * 4 + j] = xA;
            if (nB < n_nodes) PR[(size_t)nB * 128 + cg * 4 + j] = xB;
        }
    }

    // Q = nf @ W1b
#pragma unroll
    for (int p = 0; p < 4; p++)
#pragma unroll
        for (int j = 0; j < 4; j++) acc[p][j] = 0ull;
#pragma unroll 8
    for (int k = 0; k < 64; k++)
        step128(acc, mW1 + (size_t)(64 + k) * 128, s_nfT + k * 64 + nb, cg);

#pragma unroll
    for (int p = 0; p < 4; p++) {
        int nA = n0 + nb + 2 * p, nB = nA + 1;
#pragma unroll
        for (int j = 0; j < 4; j++) {
            float xA, xB; unpack2(acc[p][j], xA, xB);
            if (nA < n_nodes) Qv[(size_t)nA * 128 + cg * 4 + j] = xA;
            if (nB < n_nodes) Qv[(size_t)nB * 128 + cg * 4 + j] = xB;
        }
    }
}

// ---------------------------------------------------------------------------
// K2: node update MLP: out = nf + relu(cat(nf,st)@uW1 + ub1)@uW2 + ub2
//     Also zeros the aggregation half of the output.
// Tile: 64 nodes / block, 256 threads.
// ---------------------------------------------------------------------------
__global__ __launch_bounds__(256) void update_kernel(
    const float* __restrict__ nf, const float* __restrict__ st,
    const float* __restrict__ uW1, const float* __restrict__ ub1,
    const float* __restrict__ uW2, const float* __restrict__ ub2,
    float* __restrict__ out_nodes, float* __restrict__ agg, int n_nodes)
{
    __shared__ __align__(16) float s_buf[128 * 64];  // uT[96][64] then hT[128][64]
    __shared__ float s_ub1[128];
    __shared__ float s_ub2[64];
    const int tid = threadIdx.x;
    const int n0 = blockIdx.x * 64;

    // zero the aggregation rows for this tile (must happen before edge kernel)
    for (int i = tid; i < 64 * 64; i += 256) {
        int n = n0 + (i >> 6);
        if (n < n_nodes) agg[(size_t)n * 64 + (i & 63)] = 0.f;
    }
    for (int i = tid; i < 192; i += 256) {
        if (i < 128) s_ub1[i] = ub1[i];
        else         s_ub2[i - 128] = ub2[i - 128];
    }
    // load transposed input: rows 0..63 = nf, rows 64..95 = st
    for (int s = tid; s < 64 * 16; s += 256) {
        int n = s >> 4, k4 = s & 15;
        int ng = min(n0 + n, n_nodes - 1);
        float4 v = __ldg(reinterpret_cast<const float4*>(nf) + (size_t)ng * 16 + k4);
        s_buf[(k4 * 4 + 0) * 64 + n] = v.x;
        s_buf[(k4 * 4 + 1) * 64 + n] = v.y;
        s_buf[(k4 * 4 + 2) * 64 + n] = v.z;
        s_buf[(k4 * 4 + 3) * 64 + n] = v.w;
    }
    for (int s = tid; s < 64 * 8; s += 256) {
        int n = s >> 3, k4 = s & 7;
        int ng = min(n0 + n, n_nodes - 1);
        float4 v = __ldg(reinterpret_cast<const float4*>(st) + (size_t)ng * 8 + k4);
        s_buf[(64 + k4 * 4 + 0) * 64 + n] = v.x;
        s_buf[(64 + k4 * 4 + 1) * 64 + n] = v.y;
        s_buf[(64 + k4 * 4 + 2) * 64 + n] = v.z;
        s_buf[(64 + k4 * 4 + 3) * 64 + n] = v.w;
    }
    __syncthreads();

    const int cg = tid & 31;
    const int nb = (tid >> 5) * 8;

    u64 acc[4][4];
#pragma unroll
    for (int p = 0; p < 4; p++)
#pragma unroll
        for (int j = 0; j < 4; j++) acc[p][j] = 0ull;
#pragma unroll 8
    for (int k = 0; k < 96; k++)
        step128(acc, uW1 + (size_t)k * 128, s_buf + k * 64 + nb, cg);

    __syncthreads();  // all reads of uT done before overwrite with hT
#pragma unroll
    for (int p = 0; p < 4; p++) {
        int eA = nb + 2 * p;
#pragma unroll
        for (int j = 0; j < 4; j++) {
            float xA, xB; unpack2(acc[p][j], xA, xB);
            float bb = s_ub1[cg * 4 + j];
            xA = fmaxf(xA + bb, 0.f);
            xB = fmaxf(xB + bb, 0.f);
            *reinterpret_cast<u64*>(s_buf + (cg * 4 + j) * 64 + eA) = pack2(xA, xB);
        }
    }
    __syncthreads();

    u64 acc2[4][2];
#pragma unroll
    for (int p = 0; p < 4; p++) { acc2[p][0] = 0ull; acc2[p][1] = 0ull; }
#pragma unroll 8
    for (int k = 0; k < 128; k++)
        step64(acc2, uW2 + (size_t)k * 64, s_buf + k * 64 + nb, cg);

    const int c2 = cg * 2;
    float b0 = s_ub2[c2], b1v = s_ub2[c2 + 1];
#pragma unroll
    for (int p = 0; p < 4; p++) {
        int nA = n0 + nb + 2 * p, nB = nA + 1;
        float xA, xB, yA, yB;
        unpack2(acc2[p][0], xA, xB);
        unpack2(acc2[p][1], yA, yB);
        if (nA < n_nodes) {
            float2 r = __ldg(reinterpret_cast<const float2*>(nf + (size_t)nA * 64 + c2));
            float2 o; o.x = xA + b0 + r.x; o.y = yA + b1v + r.y;
            *reinterpret_cast<float2*>(out_nodes + (size_t)nA * 64 + c2) = o;
        }
        if (nB < n_nodes) {
            float2 r = __ldg(reinterpret_cast<const float2*>(nf + (size_t)nB * 64 + c2));
            float2 o; o.x = xB + b0 + r.x; o.y = yB + b1v + r.y;
            *reinterpret_cast<float2*>(out_nodes + (size_t)nB * 64 + c2) = o;
        }
    }
}

// ---------------------------------------------------------------------------
// K3: per-edge message MLP + atomic aggregation.
//   h1 = relu(ef@W1c + PR[src] + Q[dst] + b1)
//   h2 = relu(h1@W2 + b2)
//   msg = h2@W3 + b3  -> atomicAdd into agg[dst]
// Tile: 64 edges / block, 256 threads. Activations live transposed in smem,
// h1 and h2 share one buffer (sync-guarded overwrite).
// ---------------------------------------------------------------------------
__global__ __launch_bounds__(256) void edge_kernel(
    const float* __restrict__ ef, const int* __restrict__ eidx,
    const float* __restrict__ mW1, const float* __restrict__ mb1,
    const float* __restrict__ mW2, const float* __restrict__ mb2,
    const float* __restrict__ mW3, const float* __restrict__ mb3,
    const float* __restrict__ PR, const float* __restrict__ Qv,
    float* __restrict__ agg, int n_edges)
{
    __shared__ __align__(16) float s_efT[32 * 64];   // [k][edge]
    __shared__ __align__(16) float s_hT[128 * 64];   // h1 then h2, [c][edge]
    __shared__ int s_src[64], s_dst[64];
    __shared__ float s_b1[128], s_b2[128], s_b3[64];

    const int tid = threadIdx.x;
    const int e0 = blockIdx.x * 64;

    if (tid < 64) {
        int ee = min(e0 + tid, n_edges - 1);
        int2 pr_ = __ldg(reinterpret_cast<const int2*>(eidx) + ee);
        s_src[tid] = pr_.x;
        s_dst[tid] = pr_.y;
    }
    for (int i = tid; i < 320; i += 256) {
        if (i < 128)      s_b1[i] = mb1[i];
        else if (i < 256) s_b2[i - 128] = mb2[i - 128];
        else              s_b3[i - 256] = mb3[i - 256];
    }
    for (int s = tid; s < 64 * 8; s += 256) {
        int e = s >> 3, k4 = s & 7;
        int ee = min(e0 + e, n_edges - 1);
        float4 v = __ldg(reinterpret_cast<const float4*>(ef) + (size_t)ee * 8 + k4);
        s_efT[(k4 * 4 + 0) * 64 + e] = v.x;
        s_efT[(k4 * 4 + 1) * 64 + e] = v.y;
        s_efT[(k4 * 4 + 2) * 64 + e] = v.z;
        s_efT[(k4 * 4 + 3) * 64 + e] = v.w;
    }
    __syncthreads();

    const int cg = tid & 31;
    const int nb = (tid >> 5) * 8;

    // ---- layer 1 (K=32, W1c = mW1 rows 128..159) ----
    u64 acc[4][4];
#pragma unroll
    for (int p = 0; p < 4; p++)
#pragma unroll
        for (int j = 0; j < 4; j++) acc[p][j] = 0ull;
#pragma unroll 8
    for (int k = 0; k < 32; k++)
        step128(acc, mW1 + (size_t)(128 + k) * 128, s_efT + k * 64 + nb, cg);

    // epilogue: + PR[src] + Q[dst] + b1, relu, write transposed h1
#pragma unroll
    for (int p = 0; p < 4; p++) {
        int eA = nb + 2 * p, eB = eA + 1;
        int sA = s_src[eA], sB = s_src[eB];
        int dA = s_dst[eA], dB = s_dst[eB];
        float4 prA = __ldg(reinterpret_cast<const float4*>(PR + (size_t)sA * 128 + cg * 4));
        float4 prB = __ldg(reinterpret_cast<const float4*>(PR + (size_t)sB * 128 + cg * 4));
        float4 qA  = __ldg(reinterpret_cast<const float4*>(Qv + (size_t)dA * 128 + cg * 4));
        float4 qB  = __ldg(reinterpret_cast<const float4*>(Qv + (size_t)dB * 128 + cg * 4));
        float pa[4] = {prA.x, prA.y, prA.z, prA.w};
        float pb[4] = {prB.x, prB.y, prB.z, prB.w};
        float qa[4] = {qA.x, qA.y, qA.z, qA.w};
        float qb[4] = {qB.x, qB.y, qB.z, qB.w};
#pragma unroll
        for (int j = 0; j < 4; j++) {
            float xA, xB; unpack2(acc[p][j], xA, xB);
            float bb = s_b1[cg * 4 + j];
            xA = fmaxf(xA + pa[j] + qa[j] + bb, 0.f);
            xB = fmaxf(xB + pb[j] + qb[j] + bb, 0.f);
            *reinterpret_cast<u64*>(s_hT + (cg * 4 + j) * 64 + eA) = pack2(xA, xB);
        }
    }
    __syncthreads();

    // ---- layer 2 (K=128) ----
    u64 acc2[4][4];
#pragma unroll
    for (int p = 0; p < 4; p++)
#pragma unroll
        for (int j = 0; j < 4; j++) acc2[p][j] = 0ull;
#pragma unroll 8
    for (int k = 0; k < 128; k++)
        step128(acc2, mW2 + (size_t)k * 128, s_hT + k * 64 + nb, cg);

    __syncthreads();  // all h1 reads done before overwriting with h2
#pragma unroll
    for (int p = 0; p < 4; p++) {
        int eA = nb + 2 * p;
#pragma unroll
        for (int j = 0; j < 4; j++) {
            float xA, xB; unpack2(acc2[p][j], xA, xB);
            float bb = s_b2[cg * 4 + j];
            xA = fmaxf(xA + bb, 0.f);
            xB = fmaxf(xB + bb, 0.f);
            *reinterpret_cast<u64*>(s_hT + (cg * 4 + j) * 64 + eA) = pack2(xA, xB);
        }
    }
    __syncthreads();

    // ---- layer 3 (K=128, 64 out cols) ----
    u64 acc3[4][2];
#pragma unroll
    for (int p = 0; p < 4; p++) { acc3[p][0] = 0ull; acc3[p][1] = 0ull; }
#pragma unroll 8
    for (int k = 0; k < 128; k++)
        step64(acc3, mW3 + (size_t)k * 64, s_hT + k * 64 + nb, cg);

    const int c2 = cg * 2;
    float bb0 = s_b3[c2], bb1 = s_b3[c2 + 1];
#pragma unroll
    for (int p = 0; p < 4; p++) {
        int eA = nb + 2 * p, eB = eA + 1;
        float xA, xB, yA, yB;
        unpack2(acc3[p][0], xA, xB);
        unpack2(acc3[p][1], yA, yB);
        if (e0 + eA < n_edges) {
            int dA = s_dst[eA];
            atomicAdd(agg + (size_t)dA * 64 + c2,     xA + bb0);
            atomicAdd(agg + (size_t)dA * 64 + c2 + 1, yA + bb1);
        }
        if (e0 + eB < n_edges) {
            int dB = s_dst[eB];
            atomicAdd(agg + (size_t)dB * 64 + c2,     xB + bb0);
            atomicAdd(agg + (size_t)dB * 64 + c2 + 1, yB + bb1);
        }
    }
}

// ---------------------------------------------------------------------------
extern "C" void kernel_launch(void* const* d_in, const int* in_sizes, int n_in,
                              void* d_out, int out_size)
{
    const float* nf  = (const float*)d_in[0];
    const float* ef  = (const float*)d_in[1];
    const float* st  = (const float*)d_in[2];
    const float* mW1 = (const float*)d_in[3];
    const float* mb1 = (const float*)d_in[4];
    const float* mW2 = (const float*)d_in[5];
    const float* mb2 = (const float*)d_in[6];
    const float* mW3 = (const float*)d_in[7];
    const float* mb3 = (const float*)d_in[8];
    const float* uW1 = (const float*)d_in[9];
    const float* ub1 = (const float*)d_in[10];
    const float* uW2 = (const float*)d_in[11];
    const float* ub2 = (const float*)d_in[12];
    const int*   eidx = (const int*)d_in[13];

    const int n_nodes = in_sizes[0] / 64;
    const int n_edges = in_sizes[1] / 32;

    float* out_nodes = (float*)d_out;
    float* agg = out_nodes + (size_t)n_nodes * 64;

    float *PR = nullptr, *Qv = nullptr;
    cudaGetSymbolAddress((void**)&PR, g_PR);
    cudaGetSymbolAddress((void**)&Qv, g_Q);

    const int nblocks = (n_nodes + 63) / 64;
    const int eblocks = (n_edges + 63) / 64;

    node_pre_kernel<<<nblocks, 256>>>(nf, st, mW1, PR, Qv, n_nodes);
    update_kernel<<<nblocks, 256>>>(nf, st, uW1, ub1, uW2, ub2, out_nodes, agg, n_nodes);
    edge_kernel<<<eblocks, 256>>>(ef, eidx, mW1, mb1, mW2, mb2, mW3, mb3, PR, Qv, agg, n_edges);
}